// round 9
// baseline (speedup 1.0000x reference)
#include <cuda_runtime.h>

// ============================================================================
// EstimateCentroids, ONE persistent kernel (grid = #SMs, software barriers):
//   A: binarize + z-erosion (bit-packed)            -> g_zbits
//   B: y- then x-erosion (shared tiles)             -> g_xbits
//   C: hash-binned packed-u64 shared-atomic sums    -> g_acc*  (2x unroll)
//   D: packed-key stable rank sort + scatter (ldcg) -> g_bsort/g_order/bits
//   E: last block (done-counter) resets barrier counters for the next graph
//      replay, then runs greedy NMS + keep output.
// ============================================================================

#define XD 512
#define YD 512
#define ZD 48
#define NROWS (XD * YD)              // 262144
#define NVOX  (NROWS * ZD)           // 12582912
#define NQUADS (NVOX / 4)            // 3145728
#define NCHUNKS (NQUADS / 3072)      // 1024
#define NBINS 4096
#define NWORDS 64

typedef unsigned long long u64;

// ---------------- device scratch (static: no allocations allowed) -----------
__device__ u64 g_zbits[NROWS];
__device__ u64 g_xbits[NROWS];
__device__ u64 g_acc1[NBINS];        // (sx+256c)<<32 | (sy+256c)
__device__ u64 g_acc2[NBINS];        // (sz+256c)<<32 | c
__device__ float4 g_bsort[NBINS];
__device__ int    g_order[NBINS];
__device__ u64 g_clusterbits[NWORDS];
__device__ unsigned int g_bar[4];    // grid-barrier counters
__device__ unsigned int g_done;      // phase-E completion counter

// ---------------- software grid barrier (all blocks resident) ---------------
__device__ __forceinline__ void grid_bar(int phase) {
    __threadfence();                  // each thread flushes its own writes
    __syncthreads();
    if (threadIdx.x == 0) {
        atomicAdd(&g_bar[phase], 1u);
        while (*(volatile unsigned int*)&g_bar[phase] < gridDim.x)
            __nanosleep(64);
    }
    __syncthreads();
}

// ---------------- phase C per-voxel helper ----------------------------------
__device__ __forceinline__ void accum_quad(u64* sbins, unsigned int m4,
                                           float4 fa, float4 fb, float4 fc) {
    float ax[4]  = {fa.x, fa.y, fa.z, fa.w};
    float bx[4]  = {fb.x, fb.y, fb.z, fb.w};
    float cx4[4] = {fc.x, fc.y, fc.z, fc.w};
    #pragma unroll
    for (int k = 0; k < 4; k++) {
        if (!((m4 >> k) & 1u)) continue;
        float a = ax[k], b = bx[k], c2 = cx4[k];
        if (a > -2.0f || b > -2.0f || c2 > -2.0f) {
            int cx = __float2int_rn(a * 25.0f);   // round-half-even == jnp.round
            int cy = __float2int_rn(b * 25.0f);
            int cz = __float2int_rn(c2 * 25.0f);
            unsigned int qx = (unsigned int)min(max(cx + 128, 0), 255);
            unsigned int qy = (unsigned int)min(max(cy + 128, 0), 255);
            unsigned int qz = (unsigned int)min(max(cz + 128, 0), 255);
            unsigned int h = qx * 73856093u ^ qy * 19349663u ^ qz * 83492791u;
            unsigned int seg = h & (NBINS - 1);
            u64 p = (1ULL << 48) |
                    ((u64)(unsigned int)(cx + 256) << 32) |
                    ((u64)(unsigned int)(cy + 256) << 16) |
                    (u64)(unsigned int)(cz + 256);
            atomicAdd(&sbins[seg], p);
        }
    }
}

// ============================================================================
__global__ void __launch_bounds__(1024, 1) mega_kernel(const float* __restrict__ emb,
                                                       const float* __restrict__ pm,
                                                       float* __restrict__ out,
                                                       int out_size) {
    __shared__ __align__(16) unsigned char smem_raw[32768];
    __shared__ u64 cand[NWORDS];
    __shared__ u64 kept[NWORDS];
    __shared__ int cur_i;
    __shared__ unsigned int is_last;
    int tid = threadIdx.x;

    // -------- phase A: binarize + z-erosion, 3072 quads (256 rows) per chunk
    {
        unsigned char* nib = smem_raw;
        const float4* pm4 = (const float4*)pm;
        for (int c = blockIdx.x; c < NCHUNKS; c += gridDim.x) {
            __syncthreads();          // protect nib reuse across chunks
            #pragma unroll
            for (int r = 0; r < 3; r++) {
                float4 v = pm4[c * 3072 + r * 1024 + tid];
                unsigned int n = (v.x > 0.5f ? 1u : 0u) | (v.y > 0.5f ? 2u : 0u) |
                                 (v.z > 0.5f ? 4u : 0u) | (v.w > 0.5f ? 8u : 0u);
                nib[r * 1024 + tid] = (unsigned char)n;
            }
            __syncthreads();
            if (tid < 256) {
                u64 b = 0ULL;
                #pragma unroll
                for (int k = 0; k < 12; k++)
                    b |= (u64)nib[tid * 12 + k] << (4 * k);
                u64 e = b;
                #pragma unroll
                for (int k = 1; k <= 4; k++)
                    e &= (b >> k) & (b << k);
                e &= 0x0000FFFFFFFFFFFFULL;
                g_zbits[c * 256 + tid] = e;
            }
        }
        // fused zeroing of accumulator arrays (done before barrier 0)
        if (blockIdx.x == 0) {
            for (int l = tid; l < NBINS; l += 1024) { g_acc1[l] = 0ULL; g_acc2[l] = 0ULL; }
            if (tid < NWORDS) g_clusterbits[tid] = 0ULL;
        }
    }
    grid_bar(0);

    // -------- phase B: y then x erosion, 32x32-row tiles with 4-halo --------
    {
        u64* szt = (u64*)smem_raw;                     // [40*40]
        u64* syt = (u64*)(smem_raw + 12800);           // [40*32]
        for (int t = blockIdx.x; t < 256; t += gridDim.x) {
            __syncthreads();
            int x0 = (t >> 4) * 32, y0 = (t & 15) * 32;
            for (int l = tid; l < 1600; l += 1024) {
                int xx = l / 40, yy = l - xx * 40;
                int gx = x0 + xx - 4, gy = y0 + yy - 4;
                u64 v = 0ULL;
                if (gx >= 0 && gx < XD && gy >= 0 && gy < YD)
                    v = g_zbits[gx * YD + gy];
                szt[xx * 40 + yy] = v;
            }
            __syncthreads();
            for (int l = tid; l < 1280; l += 1024) {
                int xx = l >> 5, yy = l & 31;
                int gy = y0 + yy;
                u64 r = 0ULL;
                if (gy >= 4 && gy <= YD - 5) {
                    r = ~0ULL;
                    #pragma unroll
                    for (int dy = 0; dy <= 8; dy++)
                        r &= szt[xx * 40 + yy + dy];
                }
                syt[xx * 32 + yy] = r;
            }
            __syncthreads();
            {
                int xx = tid >> 5, yy = tid & 31;
                int gx = x0 + xx;
                u64 r = 0ULL;
                if (gx >= 4 && gx <= XD - 5) {
                    r = ~0ULL;
                    #pragma unroll
                    for (int dx = 0; dx <= 8; dx++)
                        r &= syt[(xx + dx) * 32 + yy];
                }
                g_xbits[gx * YD + (y0 + yy)] = r;
            }
        }
    }
    grid_bar(1);

    // -------- phase C: hash-binned packed accumulation (2x unrolled) --------
    {
        u64* sbins = (u64*)smem_raw;
        for (int i = tid; i < NBINS; i += 1024) sbins[i] = 0ULL;
        __syncthreads();

        const float4* __restrict__ p0 = (const float4*)emb;
        const float4* __restrict__ p1 = (const float4*)(emb + NVOX);
        const float4* __restrict__ p2 = (const float4*)(emb + 2 * NVOX);

        int stride = gridDim.x * 1024;
        for (int q = blockIdx.x * 1024 + tid; q < NQUADS; q += 2 * stride) {
            int q2 = q + stride;
            bool ok2 = q2 < NQUADS;
            unsigned int rowa = (unsigned int)q / 12u;
            unsigned int zca = (unsigned int)q - rowa * 12u;
            unsigned int m4a = (unsigned int)(g_xbits[rowa] >> (zca * 4)) & 0xFu;
            unsigned int m4b = 0;
            if (ok2) {
                unsigned int rowb = (unsigned int)q2 / 12u;
                unsigned int zcb = (unsigned int)q2 - rowb * 12u;
                m4b = (unsigned int)(g_xbits[rowb] >> (zcb * 4)) & 0xFu;
            }
            float4 A0, A1, A2, B0, B1, B2;
            if (m4a) { A0 = p0[q];  A1 = p1[q];  A2 = p2[q];  }
            if (m4b) { B0 = p0[q2]; B1 = p1[q2]; B2 = p2[q2]; }
            if (m4a) accum_quad(sbins, m4a, A0, A1, A2);
            if (m4b) accum_quad(sbins, m4b, B0, B1, B2);
        }
        __syncthreads();

        for (int i = tid; i < NBINS; i += 1024) {
            u64 p = sbins[i];
            if (p) {
                u64 cnt = p >> 48;
                u64 xf = (p >> 32) & 0xFFFFULL;
                u64 yf = (p >> 16) & 0xFFFFULL;
                u64 zf = p & 0xFFFFULL;
                atomicAdd(&g_acc1[i], (xf << 32) | yf);
                atomicAdd(&g_acc2[i], (zf << 32) | cnt);
            }
        }
    }
    grid_bar(2);

    // -------- phase D: packed-key stable rank sort + scatter -----------------
    // Key k_j = ((s_j+1)<<12) | (4095-j): k_j > k_i <=> (s_j>s_i) or
    // (s_j==s_i && j<i), so rank(i) = #{j : k_j > k_i} == argsort(-s) rank.
    // g_acc* read with __ldcg: block 0's L1 holds stale zeroed lines from A.
    {
        int* skey = (int*)smem_raw;
        for (int l = tid; l < NBINS; l += 1024) {
            int cnt = (int)(__ldcg(&g_acc2[l]) & 0xFFFFFFFFULL);
            int s = (cnt >= 10) ? cnt : -1;
            skey[l] = ((s + 1) << 12) | (NBINS - 1 - l);
        }
        __syncthreads();

        int w = tid >> 5;
        int lane = tid & 31;
        const int4* k4 = (const int4*)skey;
        for (int kb = blockIdx.x; kb < 128; kb += gridDim.x) {
            int i = kb * 32 + w;
            int ki = skey[i];
            int r = 0;
            #pragma unroll 8
            for (int n = 0; n < 32; n++) {
                int4 v = k4[n * 32 + lane];
                r += (v.x > ki) + (v.y > ki) + (v.z > ki) + (v.w > ki);
            }
            #pragma unroll
            for (int d = 1; d < 32; d <<= 1)
                r += __shfl_xor_sync(0xFFFFFFFFu, r, d);

            if (lane == 0) {
                u64 a1 = __ldcg(&g_acc1[i]);
                u64 a2 = __ldcg(&g_acc2[i]);
                int cnt = (int)(a2 & 0xFFFFFFFFULL);
                int sx = (int)(a1 >> 32) - 256 * cnt;
                int sy = (int)(a1 & 0xFFFFFFFFULL) - 256 * cnt;
                int sz = (int)(a2 >> 32) - 256 * cnt;
                float d = fmaxf((float)cnt, 1.0f);
                float c0 = (float)sx / d;
                float c1 = (float)sy / d;
                float c2 = (float)sz / d;
                if (i * 3 + 2 < out_size) {
                    out[i * 3 + 0] = c0;
                    out[i * 3 + 1] = c1;
                    out[i * 3 + 2] = c2;
                }
                float4 bx;
                bx.x = c0 - 22.5f;
                bx.y = c1 - 22.5f;
                bx.z = c0 + 22.5f;
                bx.w = c1 + 22.5f;
                g_order[r] = i;
                g_bsort[r] = bx;
                if (cnt >= 10)  // is_cluster
                    atomicOr(&g_clusterbits[r >> 6], 1ULL << (r & 63));
            }
        }
    }

    // -------- phase E: last block runs greedy NMS + keep output -------------
    __threadfence();
    __syncthreads();
    if (tid == 0)
        is_last = (atomicAdd(&g_done, 1u) == gridDim.x - 1) ? 1u : 0u;
    __syncthreads();
    if (!is_last) return;

    // reset counters for the next graph replay (safe: every other block's
    // final g_bar/g_done access happened before g_done reached gridDim, and
    // the next launch is stream-serialized after this one).
    if (tid < 4) g_bar[tid] = 0;
    if (tid == 0) g_done = 0;

    // All other blocks' phase-D stores are L2-visible (fence before counter).
    // This block's L1 may hold stale lines it part-wrote -> __ldcg everywhere.
    if (tid < NWORDS) {
        cand[tid] = __ldcg(&g_clusterbits[tid]);
        kept[tid] = 0ULL;
    }

    float4 bj[4];
    float a2v[4];
    #pragma unroll
    for (int k = 0; k < 4; k++) {
        const float4* bp = &g_bsort[tid * 4 + k];
        bj[k].x = __ldcg(&bp->x);
        bj[k].y = __ldcg(&bp->y);
        bj[k].z = __ldcg(&bp->z);
        bj[k].w = __ldcg(&bp->w);
        a2v[k] = (bj[k].z - bj[k].x) * (bj[k].w - bj[k].y);
    }
    __syncthreads();

    while (true) {
        if (tid == 0) {
            int found = -1;
            for (int ww = 0; ww < NWORDS; ww++) {
                u64 cw = cand[ww];
                if (cw) { found = (ww << 6) + __ffsll((long long)cw) - 1; break; }
            }
            cur_i = found;
            if (found >= 0) {
                kept[found >> 6] |= 1ULL << (found & 63);
                cand[found >> 6] &= ~(1ULL << (found & 63));
            }
        }
        __syncthreads();
        int ii = cur_i;
        if (ii < 0) break;
        float4 bi;
        {
            const float4* bp = &g_bsort[ii];
            bi.x = __ldcg(&bp->x);
            bi.y = __ldcg(&bp->y);
            bi.z = __ldcg(&bp->z);
            bi.w = __ldcg(&bp->w);
        }
        float a1 = (bi.z - bi.x) * (bi.w - bi.y);
        unsigned int sup4 = 0;
        #pragma unroll
        for (int k = 0; k < 4; k++) {
            int j = tid * 4 + k;
            float xx1 = fmaxf(bi.x, bj[k].x);
            float yy1 = fmaxf(bi.y, bj[k].y);
            float xx2 = fminf(bi.z, bj[k].z);
            float yy2 = fminf(bi.w, bj[k].w);
            float inter = fmaxf(xx2 - xx1, 0.0f) * fmaxf(yy2 - yy1, 0.0f);
            float iou = inter / fmaxf(a1 + a2v[k] - inter, 1e-9f);
            if (j > ii && iou > 0.5f) sup4 |= 1u << k;
        }
        if (sup4)
            atomicAnd(&cand[tid >> 4],
                      ~((u64)sup4 << ((tid & 15) * 4)));
        __syncthreads();
    }

    #pragma unroll
    for (int k = 0; k < 4; k++) {
        int rr = tid * 4 + k;
        float v = (float)((kept[rr >> 6] >> (rr & 63)) & 1ULL);
        int pos = 3 * NBINS + __ldcg(&g_order[rr]);
        if (pos < out_size) out[pos] = v;
    }
}

// ============================================================================
extern "C" void kernel_launch(void* const* d_in, const int* in_sizes, int n_in,
                              void* d_out, int out_size) {
    const float* emb = (const float*)d_in[0];   // (1,3,512,512,48) float32
    const float* pm  = (const float*)d_in[1];   // (1,1,512,512,48) float32
    float* out = (float*)d_out;

    static int sms = 0;
    if (sms == 0) cudaDeviceGetAttribute(&sms, cudaDevAttrMultiProcessorCount, 0);

    mega_kernel<<<sms, 1024>>>(emb, pm, out, out_size);
}